// round 3
// baseline (speedup 1.0000x reference)
#include <cuda_runtime.h>
#include <cuda_bf16.h>

// CBOW negative-sampling loss.
// Inputs (metadata order):
//   d_in[0] i_emb        float32  (VOCAB+1, 50)
//   d_in[1] o_emb        float32  (VOCAB+1, 50)
//   d_in[2] target_wids  int32    (B,)
//   d_in[3] context_wids int32    (B, 10)
//   d_in[4] neg_wids     int32    (B, 10)
// Output: scalar float32 = -( sum log_sigmoid(pos) + sum log_sigmoid(-neg) )

#define DIM  50
#define CTX  10
#define NNEG 10

__device__ double g_accum;

__device__ __forceinline__ float log_sigmoid(float x) {
    // numerically stable: min(x,0) - log1p(exp(-|x|))
    return fminf(x, 0.0f) - log1pf(__expf(-fabsf(x)));
}

__global__ void cbow_zero_kernel() {
    g_accum = 0.0;
}

__global__ void __launch_bounds__(256) cbow_main_kernel(
    const float* __restrict__ i_emb,
    const float* __restrict__ o_emb,
    const int*   __restrict__ target_wids,
    const int*   __restrict__ context_wids,
    const int*   __restrict__ neg_wids,
    int B)
{
    const int warp_global = (blockIdx.x * blockDim.x + threadIdx.x) >> 5;
    const int lane        = threadIdx.x & 31;
    const int warp_local  = threadIdx.x >> 5;

    __shared__ float s_partial[8];

    float loss = 0.0f;

    if (warp_global < B) {
        const int  d0     = lane;        // always < 50
        const int  d1     = lane + 32;   // valid iff lane < 18
        const bool has_d1 = (d1 < DIM);

        // ---- average context embedding (registers, per-lane 2 dims) ----
        const int* __restrict__ cw = context_wids + warp_global * CTX;
        float a0 = 0.0f, a1 = 0.0f;
        #pragma unroll
        for (int c = 0; c < CTX; c++) {
            const long base = (long)__ldg(&cw[c]) * DIM;
            a0 += __ldg(&i_emb[base + d0]);
            if (has_d1) a1 += __ldg(&i_emb[base + d1]);
        }
        a0 *= (1.0f / CTX);
        a1 *= (1.0f / CTX);

        // ---- positive score ----
        {
            const long base = (long)__ldg(&target_wids[warp_global]) * DIM;
            float p = __ldg(&o_emb[base + d0]) * a0;
            if (has_d1) p = fmaf(__ldg(&o_emb[base + d1]), a1, p);
            #pragma unroll
            for (int o = 16; o > 0; o >>= 1)
                p += __shfl_xor_sync(0xFFFFFFFFu, p, o);
            loss += log_sigmoid(p);
        }

        // ---- negative scores ----
        const int* __restrict__ nw = neg_wids + warp_global * NNEG;
        #pragma unroll
        for (int n = 0; n < NNEG; n++) {
            const long base = (long)__ldg(&nw[n]) * DIM;
            float p = __ldg(&o_emb[base + d0]) * a0;
            if (has_d1) p = fmaf(__ldg(&o_emb[base + d1]), a1, p);
            #pragma unroll
            for (int o = 16; o > 0; o >>= 1)
                p += __shfl_xor_sync(0xFFFFFFFFu, p, o);
            loss += log_sigmoid(-p);
        }
    }

    // After the xor-butterfly, every lane of a warp holds the identical full
    // sum; lane 0 deposits it.
    if (lane == 0) s_partial[warp_local] = loss;
    __syncthreads();

    if (threadIdx.x == 0) {
        float blk = 0.0f;
        #pragma unroll
        for (int i = 0; i < 8; i++) blk += s_partial[i];
        atomicAdd(&g_accum, (double)blk);
    }
}

__global__ void cbow_finish_kernel(float* __restrict__ out) {
    out[0] = (float)(-g_accum);
}

extern "C" void kernel_launch(void* const* d_in, const int* in_sizes, int n_in,
                              void* d_out, int out_size)
{
    const float* i_emb       = (const float*)d_in[0];
    const float* o_emb       = (const float*)d_in[1];
    const int*   target_wids = (const int*)d_in[2];
    const int*   context_wids= (const int*)d_in[3];
    const int*   neg_wids    = (const int*)d_in[4];
    float*       out         = (float*)d_out;

    const int B = in_sizes[2];                 // number of batch rows
    const int warps_per_block = 256 / 32;      // 8
    const int blocks = (B + warps_per_block - 1) / warps_per_block;

    cbow_zero_kernel<<<1, 1>>>();
    cbow_main_kernel<<<blocks, 256>>>(i_emb, o_emb, target_wids,
                                      context_wids, neg_wids, B);
    cbow_finish_kernel<<<1, 1>>>(out);
}